// round 3
// baseline (speedup 1.0000x reference)
#include <cuda_runtime.h>

// Problem constants
#define B_SZ 4096
#define T_SZ 200
#define D_SZ 64
#define P_SZ 2
#define TM1 (T_SZ - 1)   // 199

#define GRID_N 2048
#define BLOCK_N 256

// Per-block partials (overwritten every launch -> no init kernel needed)
__device__ float g_part_step[GRID_N];
__device__ float g_part_drift[GRID_N];
__device__ float g_part_gdiff[GRID_N];
__device__ unsigned int g_ticket = 0;   // reset to 0 by the finalizing block

// Reduce one float across the block; result valid on thread 0.
__device__ __forceinline__ float block_reduce(float v, float* shmem) {
    #pragma unroll
    for (int off = 16; off > 0; off >>= 1)
        v += __shfl_down_sync(0xFFFFFFFFu, v, off);
    int lane = threadIdx.x & 31;
    int wid  = threadIdx.x >> 5;
    if (lane == 0) shmem[wid] = v;
    __syncthreads();
    int nwarps = blockDim.x >> 5;
    if (wid == 0) {
        float s = (lane < nwarps) ? shmem[lane] : 0.0f;
        #pragma unroll
        for (int off = 16; off > 0; off >>= 1)
            s += __shfl_down_sync(0xFFFFFFFFu, s, off);
        return s;
    }
    return 0.0f;
}

__global__ void __launch_bounds__(BLOCK_N)
fused_kernel(const float* __restrict__ pred_params,
             const float* __restrict__ step_preds,
             const float* __restrict__ cov,
             const float* __restrict__ theta,
             const int*   __restrict__ lengths,
             float*       __restrict__ out) {
    __shared__ float shmem[32];

    // ---- Phase 1: step-ahead term (dominant traffic) ----
    // 16 lanes per (b,t) row; skip masked rows before issuing any big loads.
    {
        const int groups_per_block = BLOCK_N >> 4;
        const int gid    = blockIdx.x * groups_per_block + (threadIdx.x >> 4);
        const int lane   = threadIdx.x & 15;
        const int n_grps = GRID_N * groups_per_block;
        const int n_rows = B_SZ * TM1;

        float local = 0.0f;
        for (int row = gid; row < n_rows; row += n_grps) {
            int b = row / TM1;
            int t = row - b * TM1;
            int len = lengths[b];
            if (t >= len - 1) continue;
            float w = 1.0f / ((float)(len - 1) * (float)D_SZ);

            const float4 p = *reinterpret_cast<const float4*>(
                step_preds + (size_t)row * D_SZ + (lane << 2));
            const float* c = cov + (size_t)b * T_SZ * (D_SZ + 1)
                                 + (size_t)(t + 1) * (D_SZ + 1) + 1 + (lane << 2);
            float d0 = c[0] - p.x;
            float d1 = c[1] - p.y;
            float d2 = c[2] - p.z;
            float d3 = c[3] - p.w;
            local += w * (d0 * d0 + d1 * d1 + d2 * d2 + d3 * d3);
        }
        float s = block_reduce(local, shmem);
        if (threadIdx.x == 0) g_part_step[blockIdx.x] = s;
        __syncthreads();  // shmem reuse
    }

    // ---- Phase 2: drift + global-diff over pred_params [B,T,2] ----
    {
        const float inv_th0 = 1.0f / theta[0];
        const float inv_th1 = 1.0f / theta[1];
        const int n = B_SZ * T_SZ;
        const int stride = GRID_N * BLOCK_N;

        float drift = 0.0f;
        float gdiff = 0.0f;
        for (int i = blockIdx.x * BLOCK_N + threadIdx.x; i < n; i += stride) {
            int t = i % T_SZ;
            float2 x = reinterpret_cast<const float2*>(pred_params)[i];
            float e0 = x.x * inv_th0 - 1.0f;
            float e1 = x.y * inv_th1 - 1.0f;
            gdiff += e0 * e0 + e1 * e1;
            if (t < T_SZ - 1) {
                float2 y = reinterpret_cast<const float2*>(pred_params)[i + 1];
                float d0 = x.x - y.x;
                float d1 = x.y - y.y;
                drift += d0 * d0 + d1 * d1;
            }
        }
        float sd = block_reduce(drift, shmem);
        if (threadIdx.x == 0) g_part_drift[blockIdx.x] = sd;
        __syncthreads();
        float sg = block_reduce(gdiff, shmem);
        if (threadIdx.x == 0) g_part_gdiff[blockIdx.x] = sg;
    }

    // ---- Phase 3: last block finalizes ----
    __shared__ bool is_last;
    __threadfence();
    if (threadIdx.x == 0) {
        unsigned int t = atomicInc(&g_ticket, GRID_N - 1);
        is_last = (t == GRID_N - 1);   // atomicInc wraps to 0 on the last block
    }
    __syncthreads();
    if (!is_last) return;

    // Reduce the per-block slots in double (deterministic within a launch at
    // float level per-thread, double combine keeps error ~1e-7).
    double a0 = 0.0, a1 = 0.0, a2 = 0.0;
    for (int i = threadIdx.x; i < GRID_N; i += BLOCK_N) {
        a0 += (double)g_part_step[i];
        a1 += (double)g_part_drift[i];
        a2 += (double)g_part_gdiff[i];
    }
    // block reduce three doubles via shared
    __shared__ double dsh[3][32];
    #pragma unroll
    for (int off = 16; off > 0; off >>= 1) {
        a0 += __shfl_down_sync(0xFFFFFFFFu, a0, off);
        a1 += __shfl_down_sync(0xFFFFFFFFu, a1, off);
        a2 += __shfl_down_sync(0xFFFFFFFFu, a2, off);
    }
    int lane = threadIdx.x & 31;
    int wid  = threadIdx.x >> 5;
    if (lane == 0) { dsh[0][wid] = a0; dsh[1][wid] = a1; dsh[2][wid] = a2; }
    __syncthreads();
    if (wid == 0) {
        int nwarps = BLOCK_N >> 5;
        a0 = (lane < nwarps) ? dsh[0][lane] : 0.0;
        a1 = (lane < nwarps) ? dsh[1][lane] : 0.0;
        a2 = (lane < nwarps) ? dsh[2][lane] : 0.0;
        #pragma unroll
        for (int off = 16; off > 0; off >>= 1) {
            a0 += __shfl_down_sync(0xFFFFFFFFu, a0, off);
            a1 += __shfl_down_sync(0xFFFFFFFFu, a1, off);
            a2 += __shfl_down_sync(0xFFFFFFFFu, a2, off);
        }
        if (lane == 0) {
            double step  = a0 / (double)B_SZ;
            double drift = a1 / ((double)B_SZ * (double)TM1 * (double)P_SZ);
            double gdiff = a2 / ((double)B_SZ * (double)T_SZ * (double)P_SZ);
            out[0] = (float)(step + 0.1 * drift + 0.01 * gdiff);
        }
    }
}

extern "C" void kernel_launch(void* const* d_in, const int* in_sizes, int n_in,
                              void* d_out, int out_size) {
    const float* global_theta = (const float*)d_in[0];
    const float* pred_params  = (const float*)d_in[1];
    // d_in[2] = hidden_states: UNUSED by the reference
    const float* step_preds   = (const float*)d_in[3];
    const float* cov_trajs    = (const float*)d_in[4];
    const int*   lengths      = (const int*)d_in[5];
    float* out = (float*)d_out;

    fused_kernel<<<GRID_N, BLOCK_N>>>(pred_params, step_preds, cov_trajs,
                                      global_theta, lengths, out);
}